// round 14
// baseline (speedup 1.0000x reference)
#include <cuda_runtime.h>
#include <cuda_fp16.h>
#include <math.h>
#include <stdint.h>

#define BATCH_ 2
#define SEQ    2048
#define DIMV   4096
#define NH     32
#define NKV    8
#define HD     128
#define TOKENS (BATCH_*SEQ)   // 4096
#define NQKV   (DIMV + 2*NKV*HD)   // 6144
#define NSM    148

// ---------------- scratch (no cudaMalloc allowed) ----------------
__device__ __align__(1024) __half g_xh   [(size_t)TOKENS * DIMV];
__device__ __align__(1024) __half g_wqkvt[(size_t)NQKV * DIMV];
__device__ __align__(1024) __half g_wot  [(size_t)DIMV * DIMV];
__device__ __align__(1024) __half g_att  [(size_t)TOKENS * DIMV];
__device__ __align__(1024) __half g_qh   [(size_t)TOKENS * NH  * HD];
__device__ __align__(1024) __half g_kh   [(size_t)TOKENS * NKV * HD];
__device__ __align__(1024) __half g_vh   [(size_t)TOKENS * NKV * HD];

// ================= helpers =================
__device__ __forceinline__ uint32_t smem_u32(const void* p) {
    return (uint32_t)__cvta_generic_to_shared(p);
}
__device__ __forceinline__ void cp16(uint32_t dst, const void* src) {
    asm volatile("cp.async.cg.shared.global [%0], [%1], 16;" :: "r"(dst), "l"(src));
}
__device__ __forceinline__ void cp_commit() {
    asm volatile("cp.async.commit_group;" ::: "memory");
}
__device__ __forceinline__ void cp_wait0() {
    asm volatile("cp.async.wait_group 0;" ::: "memory");
}
__device__ __forceinline__ void ldsm4(uint32_t& r0, uint32_t& r1, uint32_t& r2, uint32_t& r3,
                                      uint32_t addr) {
    asm volatile("ldmatrix.sync.aligned.m8n8.x4.shared.b16 {%0,%1,%2,%3}, [%4];"
                 : "=r"(r0), "=r"(r1), "=r"(r2), "=r"(r3) : "r"(addr));
}
__device__ __forceinline__ void ldsm4t(uint32_t& r0, uint32_t& r1, uint32_t& r2, uint32_t& r3,
                                       uint32_t addr) {
    asm volatile("ldmatrix.sync.aligned.m8n8.x4.trans.shared.b16 {%0,%1,%2,%3}, [%4];"
                 : "=r"(r0), "=r"(r1), "=r"(r2), "=r"(r3) : "r"(addr));
}
__device__ __forceinline__ void mma16816(float* c, const uint32_t* a, uint32_t b0, uint32_t b1) {
    asm volatile(
        "mma.sync.aligned.m16n8k16.row.col.f32.f16.f16.f32 "
        "{%0,%1,%2,%3}, {%4,%5,%6,%7}, {%8,%9}, {%0,%1,%2,%3};"
        : "+f"(c[0]), "+f"(c[1]), "+f"(c[2]), "+f"(c[3])
        : "r"(a[0]), "r"(a[1]), "r"(a[2]), "r"(a[3]), "r"(b0), "r"(b1));
}
__device__ __forceinline__ uint32_t packh(float a, float b) {
    __half2 t = __floats2half2_rn(a, b);
    return *reinterpret_cast<uint32_t*>(&t);
}

// ========== persistent fp16 HMMA GEMM: 128x64 CTA tile, 3 CTAs/SM ==========
// C[M,N] = A[M,K] @ B[N,K]^T. BK=64, 2-stage, single-sync loop,
// 8 warps in 4m x 2n grid, 32x32 per warp.
#define BM 128
#define BN 64
#define BK 64
#define LDSH  144
#define ATILE (128 * LDSH)          // 18432
#define BTILE (64 * LDSH)           // 9216
#define STGH  (ATILE + BTILE)       // 27648
#define GEMM_SMEM (2 * STGH)        // 55296 -> 3 CTAs/SM
#define MT (TOKENS / BM)            // 32
#define QK_SCALE 0.08838834764831845f

__device__ __forceinline__ void load_stage(
    uint32_t sb, int s, const __half* A, const __half* B, int K, int k0, int tid)
{
    uint32_t st = sb + s * STGH;
#pragma unroll
    for (int t = 0; t < 4; t++) {               // A: 128 rows x 8 chunks = 1024
        int c = tid + t * 256;
        int row = c >> 3, ch = (c & 7) << 4;
        size_t go = ((size_t)row * K + k0) * 2 + ch;
        cp16(st + row * LDSH + ch, (const char*)A + go);
    }
#pragma unroll
    for (int t = 0; t < 2; t++) {               // B: 64 rows x 8 chunks = 512
        int c = tid + t * 256;
        int row = c >> 3, ch = (c & 7) << 4;
        size_t go = ((size_t)row * K + k0) * 2 + ch;
        cp16(st + ATILE + row * LDSH + ch, (const char*)B + go);
    }
}

__global__ void __launch_bounds__(256, 3) gemm_h(
    const __half* __restrict__ A, const __half* __restrict__ B,
    float* __restrict__ Cf,
    __half* __restrict__ Qo, __half* __restrict__ Ko, __half* __restrict__ Vo,
    const float* __restrict__ fc, const float* __restrict__ fs,
    int N, int K, int ntiles, int mode)
{
    extern __shared__ char smem[];
    uint32_t sb = smem_u32(smem);
    const int tid = threadIdx.x, wid = tid >> 5, lane = tid & 31;
    const int wm = wid & 3, wn = wid >> 2;      // 4m x 2n warps, 32x32 each

    const int a_row = wm * 32 + (lane & 15);
    const int a_col = (lane >> 4) << 3;
    const int bg = lane >> 3;
    const int b_row = wn * 32 + ((bg >> 1) << 3) + (lane & 7);
    const int b_col = (bg & 1) << 3;
    const int cr = lane >> 2, cc = (lane & 3) << 1;
    const int NIT = K / BK;

    for (int tile = blockIdx.x; tile < ntiles; tile += gridDim.x) {
        const int bm0 = (tile % MT) * BM;           // m-fastest (B-block L2 reuse)
        const int bn0 = (tile / MT) * BN;
        const __half* pA = A + (size_t)bm0 * K;
        const __half* pB = B + (size_t)bn0 * K;

        float acc[2][4][4];
#pragma unroll
        for (int i = 0; i < 2; i++)
#pragma unroll
            for (int j = 0; j < 4; j++)
#pragma unroll
                for (int r = 0; r < 4; r++) acc[i][j][r] = 0.f;

        load_stage(sb, 0, pA, pB, K, 0, tid);
        cp_commit();

        for (int it = 0; it < NIT; ++it) {
            cp_wait0();
            __syncthreads();
            if (it + 1 < NIT) {
                load_stage(sb, (it + 1) & 1, pA, pB, K, (it + 1) * BK, tid);
                cp_commit();
            }

            uint32_t st = sb + (it & 1) * STGH;
#pragma unroll
            for (int ks = 0; ks < 4; ks++) {
                uint32_t af[2][4];
#pragma unroll
                for (int mi = 0; mi < 2; mi++) {
                    uint32_t ad = st + (a_row + mi * 16) * LDSH + (a_col + ks * 16) * 2;
                    ldsm4(af[mi][0], af[mi][1], af[mi][2], af[mi][3], ad);
                }
                uint32_t bf[4][2];
#pragma unroll
                for (int p = 0; p < 2; p++) {
                    uint32_t bd = st + ATILE + (b_row + p * 16) * LDSH + (b_col + ks * 16) * 2;
                    ldsm4(bf[2*p][0], bf[2*p][1], bf[2*p+1][0], bf[2*p+1][1], bd);
                }
#pragma unroll
                for (int mi = 0; mi < 2; mi++)
#pragma unroll
                    for (int ni = 0; ni < 4; ni++)
                        mma16816(acc[mi][ni], af[mi], bf[ni][0], bf[ni][1]);
            }
        }

        if (mode == 0) {
#pragma unroll
            for (int mi = 0; mi < 2; mi++) {
                int r0 = bm0 + wm * 32 + mi * 16 + cr;
#pragma unroll
                for (int ni = 0; ni < 4; ni++) {
                    int col = bn0 + wn * 32 + ni * 8 + cc;
                    *(float2*)(Cf + (size_t)r0 * N + col) =
                        make_float2(acc[mi][ni][0], acc[mi][ni][1]);
                    *(float2*)(Cf + (size_t)(r0 + 8) * N + col) =
                        make_float2(acc[mi][ni][2], acc[mi][ni][3]);
                }
            }
        } else {
            const int kind = (bn0 < DIMV) ? 0 : (bn0 < DIMV + NKV*HD) ? 1 : 2;
#pragma unroll
            for (int mi = 0; mi < 2; mi++) {
                int r0 = bm0 + wm * 32 + mi * 16 + cr;
#pragma unroll
                for (int ni = 0; ni < 4; ni++) {
                    int col = bn0 + wn * 32 + ni * 8 + cc;
#pragma unroll
                    for (int half_ = 0; half_ < 2; half_++) {
                        int row = r0 + half_ * 8;
                        float re = acc[mi][ni][half_ * 2];
                        float im = acc[mi][ni][half_ * 2 + 1];
                        __half2 o;
                        if (kind == 2) {
                            o = __floats2half2_rn(re, im);
                            *(__half2*)(Vo + (size_t)row * (NKV*HD) + (col - DIMV - NKV*HD)) = o;
                        } else {
                            int s = row & (SEQ - 1);
                            int j = (col & 127) >> 1;
                            float c  = fc[s * 64 + j];
                            float sn = fs[s * 64 + j];
                            if (kind == 0) {
                                o = __floats2half2_rn((re * c - im * sn) * QK_SCALE,
                                                      (re * sn + im * c) * QK_SCALE);
                                *(__half2*)(Qo + (size_t)row * DIMV + col) = o;
                            } else {
                                o = __floats2half2_rn((re * c - im * sn) * 1.0f,
                                                      (re * sn + im * c) * 1.0f);
                                *(__half2*)(Ko + (size_t)row * (NKV*HD) + (col - DIMV)) = o;
                            }
                        }
                    }
                }
            }
        }
    }
}

// ================= fp32 -> fp16 convert (packed) =================
__global__ void cvt_kernel(const float* __restrict__ src, __half* __restrict__ dst, int n4)
{
    int i = blockIdx.x * blockDim.x + threadIdx.x;
    if (i >= n4) return;
    float4 v = ((const float4*)src)[i];
    __half2 a = __floats2half2_rn(v.x, v.y);
    __half2 b = __floats2half2_rn(v.z, v.w);
    ((uint2*)dst)[i] = make_uint2(*(uint32_t*)&a, *(uint32_t*)&b);
}

// ===== transpose + convert, 64x64 tiles; z selects {wq, wk, wv} ======
__global__ void __launch_bounds__(256) tcvt_qkv_kernel(
    const float* __restrict__ wq, const float* __restrict__ wk,
    const float* __restrict__ wv, __half* __restrict__ wqkvt)
{
    const int z = blockIdx.z;
    const int N = (z == 0) ? DIMV : NKV * HD;
    if (blockIdx.x * 64 >= N) return;
    const float* w = (z == 0) ? wq : (z == 1) ? wk : wv;
    __half* dst = wqkvt + ((z == 0) ? 0 : (z == 1) ? (size_t)DIMV * DIMV
                                                   : (size_t)(DIMV + NKV*HD) * DIMV);
    __shared__ float t[64][65];
    const int n0 = blockIdx.x * 64, k0 = blockIdx.y * 64;
    const int tid = threadIdx.x;
    {
        int r = tid >> 4, c4 = (tid & 15) << 2;
#pragma unroll
        for (int i = 0; i < 4; i++) {
            float4 v = *(const float4*)(w + (size_t)(k0 + r + i * 16) * N + n0 + c4);
            t[r + i * 16][c4 + 0] = v.x;
            t[r + i * 16][c4 + 1] = v.y;
            t[r + i * 16][c4 + 2] = v.z;
            t[r + i * 16][c4 + 3] = v.w;
        }
    }
    __syncthreads();
    {
        int nl = tid >> 2, kc = (tid & 3) << 4;
        __half hv[16];
#pragma unroll
        for (int i = 0; i < 16; i++)
            hv[i] = __float2half(t[kc + i][nl]);
        *(uint4*)(dst + (size_t)(n0 + nl) * DIMV + k0 + kc)     = *(uint4*)&hv[0];
        *(uint4*)(dst + (size_t)(n0 + nl) * DIMV + k0 + kc + 8) = *(uint4*)&hv[8];
    }
}

__global__ void __launch_bounds__(256) tcvt_kernel(
    const float* __restrict__ w, __half* __restrict__ t16, int K, int N)
{
    __shared__ float t[64][65];
    const int n0 = blockIdx.x * 64, k0 = blockIdx.y * 64;
    const int tid = threadIdx.x;
    {
        int r = tid >> 4, c4 = (tid & 15) << 2;
#pragma unroll
        for (int i = 0; i < 4; i++) {
            float4 v = *(const float4*)(w + (size_t)(k0 + r + i * 16) * N + n0 + c4);
            t[r + i * 16][c4 + 0] = v.x;
            t[r + i * 16][c4 + 1] = v.y;
            t[r + i * 16][c4 + 2] = v.z;
            t[r + i * 16][c4 + 3] = v.w;
        }
    }
    __syncthreads();
    {
        int nl = tid >> 2, kc = (tid & 3) << 4;
        __half hv[16];
#pragma unroll
        for (int i = 0; i < 16; i++)
            hv[i] = __float2half(t[kc + i][nl]);
        *(uint4*)(t16 + (size_t)(n0 + nl) * K + k0 + kc)     = *(uint4*)&hv[0];
        *(uint4*)(t16 + (size_t)(n0 + nl) * K + k0 + kc + 8) = *(uint4*)&hv[8];
    }
}

// ====== persistent fp16 HMMA flash attention (R13, unchanged) ======
#define AT_LDS 272
#define AT_QT  (128 * AT_LDS)
#define AT_KVT (128 * AT_LDS)
#define AT_STG (2 * AT_KVT)
#define ATTN_SMEM (AT_QT + 2 * AT_STG)      // 174080
#define N_ITEMS ((SEQ / 128) * NH * BATCH_)  // 1024

__global__ void __launch_bounds__(256, 1) attn_h(
    const __half* __restrict__ Qh, const __half* __restrict__ Kh,
    const __half* __restrict__ Vh, __half* __restrict__ Oh)
{
    extern __shared__ char sm_[];
    uint32_t sb = smem_u32(sm_);
    const int tid = threadIdx.x, wid = tid >> 5, lane = tid & 31;

    const int bg = lane >> 3;
    const int kb_row = ((bg >> 1) << 3) + (lane & 7);
    const int kb_col = (bg & 1) << 3;

    for (int w = blockIdx.x; w < N_ITEMS; w += gridDim.x) {
        const int qt = 15 - (w & 15);
        const int h = (w >> 4) & 31;
        const int b = w >> 9;
        const int q0 = qt * 128, kvh = h >> 2;
        const int nkv = qt + 1;

        const char* Qg = (const char*)(Qh + ((size_t)(b * SEQ + q0) * NH + h) * HD);
        const char* Kg = (const char*)(Kh + ((size_t)(b * SEQ) * NKV + kvh) * HD);
        const char* Vg = (const char*)(Vh + ((size_t)(b * SEQ) * NKV + kvh) * HD);

        for (int c = tid; c < 128 * 16; c += 256) {
            int r = c >> 4, ch = (c & 15) << 4;
            cp16(sb + r * AT_LDS + ch, Qg + (size_t)r * 8192 + ch);
        }
        auto load_kv = [&](int kt, int s) {
            uint32_t st = sb + AT_QT + s * AT_STG;
            size_t gof = (size_t)kt * 128 * 2048;
            for (int c = tid; c < 128 * 16; c += 256) {
                int r = c >> 4, ch = (c & 15) << 4;
                size_t g = gof + (size_t)r * 2048 + ch;
                cp16(st + r * AT_LDS + ch,          Kg + g);
                cp16(st + AT_KVT + r * AT_LDS + ch, Vg + g);
            }
        };
        load_kv(0, 0);
        cp_commit();

        uint32_t qf[8][4];
        float oacc[16][4];
#pragma unroll
        for (int i = 0; i < 16; i++)
#pragma unroll
            for (int r = 0; r < 4; r++) oacc[i][r] = 0.f;
        float mrow0 = -1e30f, mrow1 = -1e30f, lrow0 = 0.f, lrow1 = 0.f;

        for (int kt = 0; kt < nkv; kt++) {
            cp_wait0();
            __syncthreads();
            if (kt + 1 < nkv) { load_kv(kt + 1, (kt + 1) & 1); cp_commit(); }

            if (kt == 0) {
                uint32_t qa = sb + (wid * 16 + (lane & 15)) * AT_LDS + ((lane >> 4) << 3) * 2;
#pragma unroll
                for (int kc = 0; kc < 8; kc++)
                    ldsm4(qf[kc][0], qf[kc][1], qf[kc][2], qf[kc][3], qa + kc * 32);
            }
            uint32_t st = sb + AT_QT + (kt & 1) * AT_STG;

            float sacc[16][4];
#pragma unroll
            for (int i = 0; i < 16; i++)
#pragma unroll
                for (int r = 0; r < 4; r++) sacc[i][r] = 0.f;

#pragma unroll
            for (int kc = 0; kc < 8; kc++) {
#pragma unroll
                for (int pr = 0; pr < 8; pr++) {
                    uint32_t bd = st + (pr * 16 + kb_row) * AT_LDS + (kc * 16 + kb_col) * 2;
                    uint32_t k0r, k1r, k2r, k3r;
                    ldsm4(k0r, k1r, k2r, k3r, bd);
                    mma16816(sacc[2*pr],   qf[kc], k0r, k1r);
                    mma16816(sacc[2*pr+1], qf[kc], k2r, k3r);
                }
            }

            const int k0g = kt * 128;
            const int rlo = q0 + wid * 16 + (lane >> 2);
            if (kt == nkv - 1) {
#pragma unroll
                for (int nj = 0; nj < 16; nj++) {
                    int key = k0g + nj * 8 + ((lane & 3) << 1);
                    if (key     > rlo)     sacc[nj][0] = -1e30f;
                    if (key + 1 > rlo)     sacc[nj][1] = -1e30f;
                    if (key     > rlo + 8) sacc[nj][2] = -1e30f;
                    if (key + 1 > rlo + 8) sacc[nj][3] = -1e30f;
                }
            }

            float mx0 = -1e30f, mx1 = -1e30f;
#pragma unroll
            for (int nj = 0; nj < 16; nj++) {
                mx0 = fmaxf(mx0, fmaxf(sacc[nj][0], sacc[nj][1]));
                mx1 = fmaxf(mx1, fmaxf(sacc[nj][2], sacc[nj][3]));
            }
            mx0 = fmaxf(mx0, __shfl_xor_sync(0xffffffffu, mx0, 1));
            mx0 = fmaxf(mx0, __shfl_xor_sync(0xffffffffu, mx0, 2));
            mx1 = fmaxf(mx1, __shfl_xor_sync(0xffffffffu, mx1, 1));
            mx1 = fmaxf(mx1, __shfl_xor_sync(0xffffffffu, mx1, 2));
            float mn0 = fmaxf(mrow0, mx0), mn1 = fmaxf(mrow1, mx1);
            float cr0 = __expf(mrow0 - mn0), cr1 = __expf(mrow1 - mn1);
            mrow0 = mn0; mrow1 = mn1;
            float sum0 = 0.f, sum1 = 0.f;
#pragma unroll
            for (int nj = 0; nj < 16; nj++) {
                float p0 = __expf(sacc[nj][0] - mn0); sacc[nj][0] = p0; sum0 += p0;
                float p1 = __expf(sacc[nj][1] - mn0); sacc[nj][1] = p1; sum0 += p1;
                float p2 = __expf(sacc[nj][2] - mn1); sacc[nj][2] = p2; sum1 += p2;
                float p3 = __expf(sacc[nj][3] - mn1); sacc[nj][3] = p3; sum1 += p3;
            }
            sum0 += __shfl_xor_sync(0xffffffffu, sum0, 1);
            sum0 += __shfl_xor_sync(0xffffffffu, sum0, 2);
            sum1 += __shfl_xor_sync(0xffffffffu, sum1, 1);
            sum1 += __shfl_xor_sync(0xffffffffu, sum1, 2);
            lrow0 = lrow0 * cr0 + sum0;
            lrow1 = lrow1 * cr1 + sum1;
#pragma unroll
            for (int nj = 0; nj < 16; nj++) {
                oacc[nj][0] *= cr0; oacc[nj][1] *= cr0;
                oacc[nj][2] *= cr1; oacc[nj][3] *= cr1;
            }

#pragma unroll
            for (int kc = 0; kc < 8; kc++) {
                uint32_t pa[4];
                pa[0] = packh(sacc[2*kc][0],   sacc[2*kc][1]);
                pa[1] = packh(sacc[2*kc][2],   sacc[2*kc][3]);
                pa[2] = packh(sacc[2*kc+1][0], sacc[2*kc+1][1]);
                pa[3] = packh(sacc[2*kc+1][2], sacc[2*kc+1][3]);
                uint32_t vrow = st + AT_KVT + (kc * 16 + (lane & 15)) * AT_LDS
                              + ((lane >> 4) << 3) * 2;
#pragma unroll
                for (int g = 0; g < 8; g++) {
                    uint32_t v0, v1, v2, v3;
                    ldsm4t(v0, v1, v2, v3, vrow + g * 32);
                    mma16816(oacc[2*g],   pa, v0, v1);
                    mma16816(oacc[2*g+1], pa, v2, v3);
                }
            }
        }
        __syncthreads();   // item boundary: protect Q/KV smem from next item's loads

        float inv0 = 1.f / lrow0, inv1 = 1.f / lrow1;
        const int rlo = q0 + wid * 16 + (lane >> 2);
        size_t base_lo = ((size_t)(b * SEQ + rlo) * NH + h) * HD + ((lane & 3) << 1);
        size_t base_hi = base_lo + (size_t)8 * NH * HD;
#pragma unroll
        for (int nj = 0; nj < 16; nj++) {
            *(__half2*)(Oh + base_lo + nj * 8) =
                __floats2half2_rn(oacc[nj][0] * inv0, oacc[nj][1] * inv0);
            *(__half2*)(Oh + base_hi + nj * 8) =
                __floats2half2_rn(oacc[nj][2] * inv1, oacc[nj][3] * inv1);
        }
    }
}

// ============================ launch ======================================
extern "C" void kernel_launch(void* const* d_in, const int* in_sizes, int n_in,
                              void* d_out, int out_size)
{
    const float* x  = (const float*)d_in[0];
    const float* wq = (const float*)d_in[1];
    const float* wk = (const float*)d_in[2];
    const float* wv = (const float*)d_in[3];
    const float* wo = (const float*)d_in[4];
    const float* fc = (const float*)d_in[7];
    const float* fs = (const float*)d_in[8];
    float* out = (float*)d_out;
    (void)in_sizes; (void)n_in; (void)out_size;

    __half *xh, *wqkvt, *wot, *att, *qh, *kh, *vh;
    cudaGetSymbolAddress((void**)&xh,    g_xh);
    cudaGetSymbolAddress((void**)&wqkvt, g_wqkvt);
    cudaGetSymbolAddress((void**)&wot,   g_wot);
    cudaGetSymbolAddress((void**)&att,   g_att);
    cudaGetSymbolAddress((void**)&qh,    g_qh);
    cudaGetSymbolAddress((void**)&kh,    g_kh);
    cudaGetSymbolAddress((void**)&vh,    g_vh);

    cudaFuncSetAttribute(gemm_h, cudaFuncAttributeMaxDynamicSharedMemorySize, GEMM_SMEM);
    cudaFuncSetAttribute(attn_h, cudaFuncAttributeMaxDynamicSharedMemorySize, ATTN_SMEM);

    // ---- prep ----
    const int n4x = TOKENS * DIMV / 4;
    cvt_kernel<<<n4x / 256, 256>>>(x, xh, n4x);
    tcvt_qkv_kernel<<<dim3(DIMV / 64, DIMV / 64, 3), 256>>>(wq, wk, wv, wqkvt);
    tcvt_kernel<<<dim3(DIMV / 64, DIMV / 64), 256>>>(wo, wot, DIMV, DIMV);

    // ---- fused QKV projection + RoPE + fp16 epilogue (3 CTAs/SM persistent) ----
    gemm_h<<<3 * NSM, 256, GEMM_SMEM>>>(xh, wqkvt, nullptr, qh, kh, vh, fc, fs,
                                        NQKV, DIMV, MT * (NQKV / BN), 1);

    // ---- flash attention (persistent, 128-key KV tiles) ----
    attn_h<<<NSM, 256, ATTN_SMEM>>>(qh, kh, vh, att);

    // ---- output projection (fp32 out) ----
    gemm_h<<<3 * NSM, 256, GEMM_SMEM>>>(att, wot, out, nullptr, nullptr, nullptr, fc, fs,
                                        DIMV, DIMV, MT * (DIMV / BN), 0);
}

// round 15
// speedup vs baseline: 1.1033x; 1.1033x over previous
#include <cuda_runtime.h>
#include <cuda_fp16.h>
#include <math.h>
#include <stdint.h>

#define BATCH_ 2
#define SEQ    2048
#define DIMV   4096
#define NH     32
#define NKV    8
#define HD     128
#define TOKENS (BATCH_*SEQ)   // 4096
#define NQKV   (DIMV + 2*NKV*HD)   // 6144
#define NSM    148

// ---------------- scratch (no cudaMalloc allowed) ----------------
__device__ __align__(1024) __half g_xh   [(size_t)TOKENS * DIMV];
__device__ __align__(1024) __half g_wqkvt[(size_t)NQKV * DIMV];
__device__ __align__(1024) __half g_wot  [(size_t)DIMV * DIMV];
__device__ __align__(1024) __half g_att  [(size_t)TOKENS * DIMV];
__device__ __align__(1024) __half g_qh   [(size_t)TOKENS * NH  * HD];
__device__ __align__(1024) __half g_kh   [(size_t)TOKENS * NKV * HD];
__device__ __align__(1024) __half g_vh   [(size_t)TOKENS * NKV * HD];

// ================= helpers =================
__device__ __forceinline__ uint32_t smem_u32(const void* p) {
    return (uint32_t)__cvta_generic_to_shared(p);
}
__device__ __forceinline__ void cp16(uint32_t dst, const void* src) {
    asm volatile("cp.async.cg.shared.global [%0], [%1], 16;" :: "r"(dst), "l"(src));
}
__device__ __forceinline__ void cp_commit() {
    asm volatile("cp.async.commit_group;" ::: "memory");
}
__device__ __forceinline__ void cp_wait0() {
    asm volatile("cp.async.wait_group 0;" ::: "memory");
}
__device__ __forceinline__ void ldsm4(uint32_t& r0, uint32_t& r1, uint32_t& r2, uint32_t& r3,
                                      uint32_t addr) {
    asm volatile("ldmatrix.sync.aligned.m8n8.x4.shared.b16 {%0,%1,%2,%3}, [%4];"
                 : "=r"(r0), "=r"(r1), "=r"(r2), "=r"(r3) : "r"(addr));
}
__device__ __forceinline__ void ldsm4t(uint32_t& r0, uint32_t& r1, uint32_t& r2, uint32_t& r3,
                                       uint32_t addr) {
    asm volatile("ldmatrix.sync.aligned.m8n8.x4.trans.shared.b16 {%0,%1,%2,%3}, [%4];"
                 : "=r"(r0), "=r"(r1), "=r"(r2), "=r"(r3) : "r"(addr));
}
__device__ __forceinline__ void mma16816(float* c, const uint32_t* a, uint32_t b0, uint32_t b1) {
    asm volatile(
        "mma.sync.aligned.m16n8k16.row.col.f32.f16.f16.f32 "
        "{%0,%1,%2,%3}, {%4,%5,%6,%7}, {%8,%9}, {%0,%1,%2,%3};"
        : "+f"(c[0]), "+f"(c[1]), "+f"(c[2]), "+f"(c[3])
        : "r"(a[0]), "r"(a[1]), "r"(a[2]), "r"(a[3]), "r"(b0), "r"(b1));
}
__device__ __forceinline__ uint32_t packh(float a, float b) {
    __half2 t = __floats2half2_rn(a, b);
    return *reinterpret_cast<uint32_t*>(&t);
}

// ========== persistent fp16 HMMA GEMM (R13 config, single-sync loop) ======
// C[M,N] = A[M,K] @ B[N,K]^T. BM=128, BN=128, BK=64, 2-stage, 2 CTAs/SM,
// 8 warps (2m x 4n), 64x32/warp.
#define BM 128
#define BN 128
#define BK 64
#define LDSH  144
#define TILEH (128 * LDSH)
#define STGH  (2 * TILEH)
#define GEMM_SMEM (2 * STGH)       // 73728 -> 2 CTAs/SM
#define MT (TOKENS / BM)           // 32
#define QK_SCALE 0.08838834764831845f

__device__ __forceinline__ void load_stage(
    uint32_t sb, int s, const __half* A, const __half* B, int K, int k0, int tid)
{
    uint32_t st = sb + s * STGH;
#pragma unroll
    for (int t = 0; t < 4; t++) {
        int c = tid + t * 256;
        int row = c >> 3, ch = (c & 7) << 4;
        size_t go = ((size_t)row * K + k0) * 2 + ch;
        cp16(st + row * LDSH + ch,         (const char*)A + go);
        cp16(st + TILEH + row * LDSH + ch, (const char*)B + go);
    }
}

__global__ void __launch_bounds__(256, 2) gemm_h(
    const __half* __restrict__ A, const __half* __restrict__ B,
    float* __restrict__ Cf,
    __half* __restrict__ Qo, __half* __restrict__ Ko, __half* __restrict__ Vo,
    const float* __restrict__ fc, const float* __restrict__ fs,
    int N, int K, int ntiles, int mode)
{
    extern __shared__ char smem[];
    uint32_t sb = smem_u32(smem);
    const int tid = threadIdx.x, wid = tid >> 5, lane = tid & 31;
    const int wm = wid & 1, wn = wid >> 1;

    const int a_row = wm * 64 + (lane & 15);
    const int a_col = (lane >> 4) << 3;
    const int bg = lane >> 3;
    const int b_row = wn * 32 + ((bg >> 1) << 3) + (lane & 7);
    const int b_col = (bg & 1) << 3;
    const int cr = lane >> 2, cc = (lane & 3) << 1;
    const int NIT = K / BK;

    for (int tile = blockIdx.x; tile < ntiles; tile += gridDim.x) {
        const int bm0 = (tile % MT) * BM;           // m-fastest (B-block L2 reuse)
        const int bn0 = (tile / MT) * BN;
        const __half* pA = A + (size_t)bm0 * K;
        const __half* pB = B + (size_t)bn0 * K;

        float acc[4][4][4];
#pragma unroll
        for (int i = 0; i < 4; i++)
#pragma unroll
            for (int j = 0; j < 4; j++)
#pragma unroll
                for (int r = 0; r < 4; r++) acc[i][j][r] = 0.f;

        load_stage(sb, 0, pA, pB, K, 0, tid);
        cp_commit();

        for (int it = 0; it < NIT; ++it) {
            cp_wait0();
            __syncthreads();
            if (it + 1 < NIT) {
                load_stage(sb, (it + 1) & 1, pA, pB, K, (it + 1) * BK, tid);
                cp_commit();
            }

            uint32_t st = sb + (it & 1) * STGH;
#pragma unroll
            for (int ks = 0; ks < 4; ks++) {
                uint32_t af[4][4];
#pragma unroll
                for (int mi = 0; mi < 4; mi++) {
                    uint32_t ad = st + (a_row + mi * 16) * LDSH + (a_col + ks * 16) * 2;
                    ldsm4(af[mi][0], af[mi][1], af[mi][2], af[mi][3], ad);
                }
                uint32_t bf[4][2];
#pragma unroll
                for (int p = 0; p < 2; p++) {
                    uint32_t bd = st + TILEH + (b_row + p * 16) * LDSH + (b_col + ks * 16) * 2;
                    ldsm4(bf[2*p][0], bf[2*p][1], bf[2*p+1][0], bf[2*p+1][1], bd);
                }
#pragma unroll
                for (int mi = 0; mi < 4; mi++)
#pragma unroll
                    for (int ni = 0; ni < 4; ni++)
                        mma16816(acc[mi][ni], af[mi], bf[ni][0], bf[ni][1]);
            }
        }

        if (mode == 0) {
#pragma unroll
            for (int mi = 0; mi < 4; mi++) {
                int r0 = bm0 + wm * 64 + mi * 16 + cr;
#pragma unroll
                for (int ni = 0; ni < 4; ni++) {
                    int col = bn0 + wn * 32 + ni * 8 + cc;
                    *(float2*)(Cf + (size_t)r0 * N + col) =
                        make_float2(acc[mi][ni][0], acc[mi][ni][1]);
                    *(float2*)(Cf + (size_t)(r0 + 8) * N + col) =
                        make_float2(acc[mi][ni][2], acc[mi][ni][3]);
                }
            }
        } else {
            const int kind = (bn0 < DIMV) ? 0 : (bn0 < DIMV + NKV*HD) ? 1 : 2;
#pragma unroll
            for (int mi = 0; mi < 4; mi++) {
                int r0 = bm0 + wm * 64 + mi * 16 + cr;
#pragma unroll
                for (int ni = 0; ni < 4; ni++) {
                    int col = bn0 + wn * 32 + ni * 8 + cc;
#pragma unroll
                    for (int half_ = 0; half_ < 2; half_++) {
                        int row = r0 + half_ * 8;
                        float re = acc[mi][ni][half_ * 2];
                        float im = acc[mi][ni][half_ * 2 + 1];
                        __half2 o;
                        if (kind == 2) {
                            o = __floats2half2_rn(re, im);
                            *(__half2*)(Vo + (size_t)row * (NKV*HD) + (col - DIMV - NKV*HD)) = o;
                        } else {
                            int s = row & (SEQ - 1);
                            int j = (col & 127) >> 1;
                            float c  = fc[s * 64 + j];
                            float sn = fs[s * 64 + j];
                            if (kind == 0) {
                                o = __floats2half2_rn((re * c - im * sn) * QK_SCALE,
                                                      (re * sn + im * c) * QK_SCALE);
                                *(__half2*)(Qo + (size_t)row * DIMV + col) = o;
                            } else {
                                o = __floats2half2_rn((re * c - im * sn) * 1.0f,
                                                      (re * sn + im * c) * 1.0f);
                                *(__half2*)(Ko + (size_t)row * (NKV*HD) + (col - DIMV)) = o;
                            }
                        }
                    }
                }
            }
        }
    }
}

// ================= fp32 -> fp16 convert (packed) =================
__global__ void cvt_kernel(const float* __restrict__ src, __half* __restrict__ dst, int n4)
{
    int i = blockIdx.x * blockDim.x + threadIdx.x;
    if (i >= n4) return;
    float4 v = ((const float4*)src)[i];
    __half2 a = __floats2half2_rn(v.x, v.y);
    __half2 b = __floats2half2_rn(v.z, v.w);
    ((uint2*)dst)[i] = make_uint2(*(uint32_t*)&a, *(uint32_t*)&b);
}

// ===== transpose + convert, 64x64 tiles; z selects {wq, wk, wv} ======
__global__ void __launch_bounds__(256) tcvt_qkv_kernel(
    const float* __restrict__ wq, const float* __restrict__ wk,
    const float* __restrict__ wv, __half* __restrict__ wqkvt)
{
    const int z = blockIdx.z;
    const int N = (z == 0) ? DIMV : NKV * HD;
    if (blockIdx.x * 64 >= N) return;
    const float* w = (z == 0) ? wq : (z == 1) ? wk : wv;
    __half* dst = wqkvt + ((z == 0) ? 0 : (z == 1) ? (size_t)DIMV * DIMV
                                                   : (size_t)(DIMV + NKV*HD) * DIMV);
    __shared__ float t[64][65];
    const int n0 = blockIdx.x * 64, k0 = blockIdx.y * 64;
    const int tid = threadIdx.x;
    {
        int r = tid >> 4, c4 = (tid & 15) << 2;
#pragma unroll
        for (int i = 0; i < 4; i++) {
            float4 v = *(const float4*)(w + (size_t)(k0 + r + i * 16) * N + n0 + c4);
            t[r + i * 16][c4 + 0] = v.x;
            t[r + i * 16][c4 + 1] = v.y;
            t[r + i * 16][c4 + 2] = v.z;
            t[r + i * 16][c4 + 3] = v.w;
        }
    }
    __syncthreads();
    {
        int nl = tid >> 2, kc = (tid & 3) << 4;
        __half hv[16];
#pragma unroll
        for (int i = 0; i < 16; i++)
            hv[i] = __float2half(t[kc + i][nl]);
        *(uint4*)(dst + (size_t)(n0 + nl) * DIMV + k0 + kc)     = *(uint4*)&hv[0];
        *(uint4*)(dst + (size_t)(n0 + nl) * DIMV + k0 + kc + 8) = *(uint4*)&hv[8];
    }
}

__global__ void __launch_bounds__(256) tcvt_kernel(
    const float* __restrict__ w, __half* __restrict__ t16, int K, int N)
{
    __shared__ float t[64][65];
    const int n0 = blockIdx.x * 64, k0 = blockIdx.y * 64;
    const int tid = threadIdx.x;
    {
        int r = tid >> 4, c4 = (tid & 15) << 2;
#pragma unroll
        for (int i = 0; i < 4; i++) {
            float4 v = *(const float4*)(w + (size_t)(k0 + r + i * 16) * N + n0 + c4);
            t[r + i * 16][c4 + 0] = v.x;
            t[r + i * 16][c4 + 1] = v.y;
            t[r + i * 16][c4 + 2] = v.z;
            t[r + i * 16][c4 + 3] = v.w;
        }
    }
    __syncthreads();
    {
        int nl = tid >> 2, kc = (tid & 3) << 4;
        __half hv[16];
#pragma unroll
        for (int i = 0; i < 16; i++)
            hv[i] = __float2half(t[kc + i][nl]);
        *(uint4*)(t16 + (size_t)(n0 + nl) * K + k0 + kc)     = *(uint4*)&hv[0];
        *(uint4*)(t16 + (size_t)(n0 + nl) * K + k0 + kc + 8) = *(uint4*)&hv[8];
    }
}

// ====== persistent fp16 HMMA flash attention, 128-key KV, single-sync ======
#define AT_LDS 272
#define AT_QT  (128 * AT_LDS)
#define AT_KVT (128 * AT_LDS)
#define AT_STG (2 * AT_KVT)
#define ATTN_SMEM (AT_QT + 2 * AT_STG)      // 174080
#define N_ITEMS ((SEQ / 128) * NH * BATCH_)  // 1024

__global__ void __launch_bounds__(256, 1) attn_h(
    const __half* __restrict__ Qh, const __half* __restrict__ Kh,
    const __half* __restrict__ Vh, __half* __restrict__ Oh)
{
    extern __shared__ char sm_[];
    uint32_t sb = smem_u32(sm_);
    const int tid = threadIdx.x, wid = tid >> 5, lane = tid & 31;

    const int bg = lane >> 3;
    const int kb_row = ((bg >> 1) << 3) + (lane & 7);
    const int kb_col = (bg & 1) << 3;

    for (int w = blockIdx.x; w < N_ITEMS; w += gridDim.x) {
        const int qt = 15 - (w & 15);
        const int h = (w >> 4) & 31;
        const int b = w >> 9;
        const int q0 = qt * 128, kvh = h >> 2;
        const int nkv = qt + 1;

        const char* Qg = (const char*)(Qh + ((size_t)(b * SEQ + q0) * NH + h) * HD);
        const char* Kg = (const char*)(Kh + ((size_t)(b * SEQ) * NKV + kvh) * HD);
        const char* Vg = (const char*)(Vh + ((size_t)(b * SEQ) * NKV + kvh) * HD);

        for (int c = tid; c < 128 * 16; c += 256) {
            int r = c >> 4, ch = (c & 15) << 4;
            cp16(sb + r * AT_LDS + ch, Qg + (size_t)r * 8192 + ch);
        }
        auto load_kv = [&](int kt, int s) {
            uint32_t st = sb + AT_QT + s * AT_STG;
            size_t gof = (size_t)kt * 128 * 2048;
            for (int c = tid; c < 128 * 16; c += 256) {
                int r = c >> 4, ch = (c & 15) << 4;
                size_t g = gof + (size_t)r * 2048 + ch;
                cp16(st + r * AT_LDS + ch,          Kg + g);
                cp16(st + AT_KVT + r * AT_LDS + ch, Vg + g);
            }
        };
        load_kv(0, 0);
        cp_commit();

        uint32_t qf[8][4];
        float oacc[16][4];
#pragma unroll
        for (int i = 0; i < 16; i++)
#pragma unroll
            for (int r = 0; r < 4; r++) oacc[i][r] = 0.f;
        float mrow0 = -1e30f, mrow1 = -1e30f, lrow0 = 0.f, lrow1 = 0.f;

        for (int kt = 0; kt < nkv; kt++) {
            cp_wait0();
            __syncthreads();
            if (kt + 1 < nkv) { load_kv(kt + 1, (kt + 1) & 1); cp_commit(); }

            if (kt == 0) {
                uint32_t qa = sb + (wid * 16 + (lane & 15)) * AT_LDS + ((lane >> 4) << 3) * 2;
#pragma unroll
                for (int kc = 0; kc < 8; kc++)
                    ldsm4(qf[kc][0], qf[kc][1], qf[kc][2], qf[kc][3], qa + kc * 32);
            }
            uint32_t st = sb + AT_QT + (kt & 1) * AT_STG;

            float sacc[16][4];
#pragma unroll
            for (int i = 0; i < 16; i++)
#pragma unroll
                for (int r = 0; r < 4; r++) sacc[i][r] = 0.f;

#pragma unroll
            for (int kc = 0; kc < 8; kc++) {
#pragma unroll
                for (int pr = 0; pr < 8; pr++) {
                    uint32_t bd = st + (pr * 16 + kb_row) * AT_LDS + (kc * 16 + kb_col) * 2;
                    uint32_t k0r, k1r, k2r, k3r;
                    ldsm4(k0r, k1r, k2r, k3r, bd);
                    mma16816(sacc[2*pr],   qf[kc], k0r, k1r);
                    mma16816(sacc[2*pr+1], qf[kc], k2r, k3r);
                }
            }

            const int k0g = kt * 128;
            const int rlo = q0 + wid * 16 + (lane >> 2);
            if (kt == nkv - 1) {
#pragma unroll
                for (int nj = 0; nj < 16; nj++) {
                    int key = k0g + nj * 8 + ((lane & 3) << 1);
                    if (key     > rlo)     sacc[nj][0] = -1e30f;
                    if (key + 1 > rlo)     sacc[nj][1] = -1e30f;
                    if (key     > rlo + 8) sacc[nj][2] = -1e30f;
                    if (key + 1 > rlo + 8) sacc[nj][3] = -1e30f;
                }
            }

            float mx0 = -1e30f, mx1 = -1e30f;
#pragma unroll
            for (int nj = 0; nj < 16; nj++) {
                mx0 = fmaxf(mx0, fmaxf(sacc[nj][0], sacc[nj][1]));
                mx1 = fmaxf(mx1, fmaxf(sacc[nj][2], sacc[nj][3]));
            }
            mx0 = fmaxf(mx0, __shfl_xor_sync(0xffffffffu, mx0, 1));
            mx0 = fmaxf(mx0, __shfl_xor_sync(0xffffffffu, mx0, 2));
            mx1 = fmaxf(mx1, __shfl_xor_sync(0xffffffffu, mx1, 1));
            mx1 = fmaxf(mx1, __shfl_xor_sync(0xffffffffu, mx1, 2));
            float mn0 = fmaxf(mrow0, mx0), mn1 = fmaxf(mrow1, mx1);
            float cr0 = __expf(mrow0 - mn0), cr1 = __expf(mrow1 - mn1);
            mrow0 = mn0; mrow1 = mn1;
            float sum0 = 0.f, sum1 = 0.f;
#pragma unroll
            for (int nj = 0; nj < 16; nj++) {
                float p0 = __expf(sacc[nj][0] - mn0); sacc[nj][0] = p0; sum0 += p0;
                float p1 = __expf(sacc[nj][1] - mn0); sacc[nj][1] = p1; sum0 += p1;
                float p2 = __expf(sacc[nj][2] - mn1); sacc[nj][2] = p2; sum1 += p2;
                float p3 = __expf(sacc[nj][3] - mn1); sacc[nj][3] = p3; sum1 += p3;
            }
            sum0 += __shfl_xor_sync(0xffffffffu, sum0, 1);
            sum0 += __shfl_xor_sync(0xffffffffu, sum0, 2);
            sum1 += __shfl_xor_sync(0xffffffffu, sum1, 1);
            sum1 += __shfl_xor_sync(0xffffffffu, sum1, 2);
            lrow0 = lrow0 * cr0 + sum0;
            lrow1 = lrow1 * cr1 + sum1;
#pragma unroll
            for (int nj = 0; nj < 16; nj++) {
                oacc[nj][0] *= cr0; oacc[nj][1] *= cr0;
                oacc[nj][2] *= cr1; oacc[nj][3] *= cr1;
            }

#pragma unroll
            for (int kc = 0; kc < 8; kc++) {
                uint32_t pa[4];
                pa[0] = packh(sacc[2*kc][0],   sacc[2*kc][1]);
                pa[1] = packh(sacc[2*kc][2],   sacc[2*kc][3]);
                pa[2] = packh(sacc[2*kc+1][0], sacc[2*kc+1][1]);
                pa[3] = packh(sacc[2*kc+1][2], sacc[2*kc+1][3]);
                uint32_t vrow = st + AT_KVT + (kc * 16 + (lane & 15)) * AT_LDS
                              + ((lane >> 4) << 3) * 2;
#pragma unroll
                for (int g = 0; g < 8; g++) {
                    uint32_t v0, v1, v2, v3;
                    ldsm4t(v0, v1, v2, v3, vrow + g * 32);
                    mma16816(oacc[2*g],   pa, v0, v1);
                    mma16816(oacc[2*g+1], pa, v2, v3);
                }
            }
        }
        __syncthreads();   // item boundary: protect Q/KV smem from next item's loads

        float inv0 = 1.f / lrow0, inv1 = 1.f / lrow1;
        const int rlo = q0 + wid * 16 + (lane >> 2);
        size_t base_lo = ((size_t)(b * SEQ + rlo) * NH + h) * HD + ((lane & 3) << 1);
        size_t base_hi = base_lo + (size_t)8 * NH * HD;
#pragma unroll
        for (int nj = 0; nj < 16; nj++) {
            *(__half2*)(Oh + base_lo + nj * 8) =
                __floats2half2_rn(oacc[nj][0] * inv0, oacc[nj][1] * inv0);
            *(__half2*)(Oh + base_hi + nj * 8) =
                __floats2half2_rn(oacc[nj][2] * inv1, oacc[nj][3] * inv1);
        }
    }
}

// ============================ launch ======================================
extern "C" void kernel_launch(void* const* d_in, const int* in_sizes, int n_in,
                              void* d_out, int out_size)
{
    const float* x  = (const float*)d_in[0];
    const float* wq = (const float*)d_in[1];
    const float* wk = (const float*)d_in[2];
    const float* wv = (const float*)d_in[3];
    const float* wo = (const float*)d_in[4];
    const float* fc = (const float*)d_in[7];
    const float* fs = (const float*)d_in[8];
    float* out = (float*)d_out;
    (void)in_sizes; (void)n_in; (void)out_size;

    __half *xh, *wqkvt, *wot, *att, *qh, *kh, *vh;
    cudaGetSymbolAddress((void**)&xh,    g_xh);
    cudaGetSymbolAddress((void**)&wqkvt, g_wqkvt);
    cudaGetSymbolAddress((void**)&wot,   g_wot);
    cudaGetSymbolAddress((void**)&att,   g_att);
    cudaGetSymbolAddress((void**)&qh,    g_qh);
    cudaGetSymbolAddress((void**)&kh,    g_kh);
    cudaGetSymbolAddress((void**)&vh,    g_vh);

    cudaFuncSetAttribute(gemm_h, cudaFuncAttributeMaxDynamicSharedMemorySize, GEMM_SMEM);
    cudaFuncSetAttribute(attn_h, cudaFuncAttributeMaxDynamicSharedMemorySize, ATTN_SMEM);

    // ---- prep ----
    const int n4x = TOKENS * DIMV / 4;
    cvt_kernel<<<n4x / 256, 256>>>(x, xh, n4x);
    tcvt_qkv_kernel<<<dim3(DIMV / 64, DIMV / 64, 3), 256>>>(wq, wk, wv, wqkvt);
    tcvt_kernel<<<dim3(DIMV / 64, DIMV / 64), 256>>>(wo, wot, DIMV, DIMV);

    // ---- fused QKV projection + RoPE + fp16 epilogue (2 CTAs/SM persistent) ----
    gemm_h<<<2 * NSM, 256, GEMM_SMEM>>>(xh, wqkvt, nullptr, qh, kh, vh, fc, fs,
                                        NQKV, DIMV, MT * (NQKV / BN), 1);

    // ---- flash attention (persistent + queued extras for work stealing) ----
    attn_h<<<2 * NSM, 256, ATTN_SMEM>>>(qh, kh, vh, att);

    // ---- output projection (fp32 out) ----
    gemm_h<<<2 * NSM, 256, GEMM_SMEM>>>(att, wot, out, nullptr, nullptr, nullptr, fc, fs,
                                        DIMV, DIMV, MT * (DIMV / BN), 0);
}

// round 16
// speedup vs baseline: 1.1809x; 1.0703x over previous
#include <cuda_runtime.h>
#include <cuda_fp16.h>
#include <math.h>
#include <stdint.h>

#define BATCH_ 2
#define SEQ    2048
#define DIMV   4096
#define NH     32
#define NKV    8
#define HD     128
#define TOKENS (BATCH_*SEQ)   // 4096
#define NQKV   (DIMV + 2*NKV*HD)   // 6144
#define NSM    148

// ---------------- scratch (no cudaMalloc allowed) ----------------
__device__ __align__(1024) __half g_xh   [(size_t)TOKENS * DIMV];
__device__ __align__(1024) __half g_wqkvt[(size_t)NQKV * DIMV];
__device__ __align__(1024) __half g_wot  [(size_t)DIMV * DIMV];
__device__ __align__(1024) __half g_att  [(size_t)TOKENS * DIMV];
__device__ __align__(1024) __half g_qh   [(size_t)TOKENS * NH  * HD];
__device__ __align__(1024) __half g_kh   [(size_t)TOKENS * NKV * HD];
__device__ __align__(1024) __half g_vh   [(size_t)TOKENS * NKV * HD];
__device__ unsigned int g_ctr[3];   // work-steal counters: [0] qkv, [1] attn, [2] out

__global__ void reset_ctr_kernel() { g_ctr[0] = 0; g_ctr[1] = 0; g_ctr[2] = 0; }

// ================= helpers =================
__device__ __forceinline__ uint32_t smem_u32(const void* p) {
    return (uint32_t)__cvta_generic_to_shared(p);
}
__device__ __forceinline__ void cp16(uint32_t dst, const void* src) {
    asm volatile("cp.async.cg.shared.global [%0], [%1], 16;" :: "r"(dst), "l"(src));
}
__device__ __forceinline__ void cp_commit() {
    asm volatile("cp.async.commit_group;" ::: "memory");
}
__device__ __forceinline__ void cp_wait0() {
    asm volatile("cp.async.wait_group 0;" ::: "memory");
}
__device__ __forceinline__ void ldsm4(uint32_t& r0, uint32_t& r1, uint32_t& r2, uint32_t& r3,
                                      uint32_t addr) {
    asm volatile("ldmatrix.sync.aligned.m8n8.x4.shared.b16 {%0,%1,%2,%3}, [%4];"
                 : "=r"(r0), "=r"(r1), "=r"(r2), "=r"(r3) : "r"(addr));
}
__device__ __forceinline__ void ldsm4t(uint32_t& r0, uint32_t& r1, uint32_t& r2, uint32_t& r3,
                                       uint32_t addr) {
    asm volatile("ldmatrix.sync.aligned.m8n8.x4.trans.shared.b16 {%0,%1,%2,%3}, [%4];"
                 : "=r"(r0), "=r"(r1), "=r"(r2), "=r"(r3) : "r"(addr));
}
__device__ __forceinline__ void mma16816(float* c, const uint32_t* a, uint32_t b0, uint32_t b1) {
    asm volatile(
        "mma.sync.aligned.m16n8k16.row.col.f32.f16.f16.f32 "
        "{%0,%1,%2,%3}, {%4,%5,%6,%7}, {%8,%9}, {%0,%1,%2,%3};"
        : "+f"(c[0]), "+f"(c[1]), "+f"(c[2]), "+f"(c[3])
        : "r"(a[0]), "r"(a[1]), "r"(a[2]), "r"(a[3]), "r"(b0), "r"(b1));
}
__device__ __forceinline__ uint32_t packh(float a, float b) {
    __half2 t = __floats2half2_rn(a, b);
    return *reinterpret_cast<uint32_t*>(&t);
}

// ========== persistent fp16 HMMA GEMM (R13 config + tile stealing) ======
// C[M,N] = A[M,K] @ B[N,K]^T. BM=128, BN=128, BK=64, 2-stage, 2 CTAs/SM,
// 8 warps (2m x 4n), 64x32/warp, single-sync mainloop.
#define BM 128
#define BN 128
#define BK 64
#define LDSH  144
#define TILEH (128 * LDSH)
#define STGH  (2 * TILEH)
#define GEMM_SMEM (2 * STGH)       // 73728 -> 2 CTAs/SM
#define MT (TOKENS / BM)           // 32
#define QK_SCALE 0.08838834764831845f

__device__ __forceinline__ void load_stage(
    uint32_t sb, int s, const __half* A, const __half* B, int K, int k0, int tid)
{
    uint32_t st = sb + s * STGH;
#pragma unroll
    for (int t = 0; t < 4; t++) {
        int c = tid + t * 256;
        int row = c >> 3, ch = (c & 7) << 4;
        size_t go = ((size_t)row * K + k0) * 2 + ch;
        cp16(st + row * LDSH + ch,         (const char*)A + go);
        cp16(st + TILEH + row * LDSH + ch, (const char*)B + go);
    }
}

__global__ void __launch_bounds__(256, 2) gemm_h(
    const __half* __restrict__ A, const __half* __restrict__ B,
    float* __restrict__ Cf,
    __half* __restrict__ Qo, __half* __restrict__ Ko, __half* __restrict__ Vo,
    const float* __restrict__ fc, const float* __restrict__ fs,
    int N, int K, int ntiles, int mode, int ctr_idx)
{
    extern __shared__ char smem[];
    __shared__ unsigned int slot;
    uint32_t sb = smem_u32(smem);
    const int tid = threadIdx.x, wid = tid >> 5, lane = tid & 31;
    const int wm = wid & 1, wn = wid >> 1;

    const int a_row = wm * 64 + (lane & 15);
    const int a_col = (lane >> 4) << 3;
    const int bg = lane >> 3;
    const int b_row = wn * 32 + ((bg >> 1) << 3) + (lane & 7);
    const int b_col = (bg & 1) << 3;
    const int cr = lane >> 2, cc = (lane & 3) << 1;
    const int NIT = K / BK;

    while (true) {
        if (tid == 0) slot = atomicAdd(&g_ctr[ctr_idx], 1u);
        __syncthreads();
        const unsigned int tile = slot;
        if (tile >= (unsigned int)ntiles) break;

        const int bm0 = (tile % MT) * BM;           // m-fastest (B-block L2 reuse)
        const int bn0 = (tile / MT) * BN;
        const __half* pA = A + (size_t)bm0 * K;
        const __half* pB = B + (size_t)bn0 * K;

        float acc[4][4][4];
#pragma unroll
        for (int i = 0; i < 4; i++)
#pragma unroll
            for (int j = 0; j < 4; j++)
#pragma unroll
                for (int r = 0; r < 4; r++) acc[i][j][r] = 0.f;

        load_stage(sb, 0, pA, pB, K, 0, tid);
        cp_commit();

        for (int it = 0; it < NIT; ++it) {
            cp_wait0();
            __syncthreads();
            if (it + 1 < NIT) {
                load_stage(sb, (it + 1) & 1, pA, pB, K, (it + 1) * BK, tid);
                cp_commit();
            }

            uint32_t st = sb + (it & 1) * STGH;
#pragma unroll
            for (int ks = 0; ks < 4; ks++) {
                uint32_t af[4][4];
#pragma unroll
                for (int mi = 0; mi < 4; mi++) {
                    uint32_t ad = st + (a_row + mi * 16) * LDSH + (a_col + ks * 16) * 2;
                    ldsm4(af[mi][0], af[mi][1], af[mi][2], af[mi][3], ad);
                }
                uint32_t bf[4][2];
#pragma unroll
                for (int p = 0; p < 2; p++) {
                    uint32_t bd = st + TILEH + (b_row + p * 16) * LDSH + (b_col + ks * 16) * 2;
                    ldsm4(bf[2*p][0], bf[2*p][1], bf[2*p+1][0], bf[2*p+1][1], bd);
                }
#pragma unroll
                for (int mi = 0; mi < 4; mi++)
#pragma unroll
                    for (int ni = 0; ni < 4; ni++)
                        mma16816(acc[mi][ni], af[mi], bf[ni][0], bf[ni][1]);
            }
        }

        if (mode == 0) {
#pragma unroll
            for (int mi = 0; mi < 4; mi++) {
                int r0 = bm0 + wm * 64 + mi * 16 + cr;
#pragma unroll
                for (int ni = 0; ni < 4; ni++) {
                    int col = bn0 + wn * 32 + ni * 8 + cc;
                    *(float2*)(Cf + (size_t)r0 * N + col) =
                        make_float2(acc[mi][ni][0], acc[mi][ni][1]);
                    *(float2*)(Cf + (size_t)(r0 + 8) * N + col) =
                        make_float2(acc[mi][ni][2], acc[mi][ni][3]);
                }
            }
        } else {
            const int kind = (bn0 < DIMV) ? 0 : (bn0 < DIMV + NKV*HD) ? 1 : 2;
#pragma unroll
            for (int mi = 0; mi < 4; mi++) {
                int r0 = bm0 + wm * 64 + mi * 16 + cr;
#pragma unroll
                for (int ni = 0; ni < 4; ni++) {
                    int col = bn0 + wn * 32 + ni * 8 + cc;
#pragma unroll
                    for (int half_ = 0; half_ < 2; half_++) {
                        int row = r0 + half_ * 8;
                        float re = acc[mi][ni][half_ * 2];
                        float im = acc[mi][ni][half_ * 2 + 1];
                        __half2 o;
                        if (kind == 2) {
                            o = __floats2half2_rn(re, im);
                            *(__half2*)(Vo + (size_t)row * (NKV*HD) + (col - DIMV - NKV*HD)) = o;
                        } else {
                            int s = row & (SEQ - 1);
                            int j = (col & 127) >> 1;
                            float c  = fc[s * 64 + j];
                            float sn = fs[s * 64 + j];
                            if (kind == 0) {
                                o = __floats2half2_rn((re * c - im * sn) * QK_SCALE,
                                                      (re * sn + im * c) * QK_SCALE);
                                *(__half2*)(Qo + (size_t)row * DIMV + col) = o;
                            } else {
                                o = __floats2half2_rn((re * c - im * sn) * 1.0f,
                                                      (re * sn + im * c) * 1.0f);
                                *(__half2*)(Ko + (size_t)row * (NKV*HD) + (col - DIMV)) = o;
                            }
                        }
                    }
                }
            }
        }
        __syncthreads();   // protect smem stages + slot before next tile fetch
    }
}

// ================= fp32 -> fp16 convert (packed) =================
__global__ void cvt_kernel(const float* __restrict__ src, __half* __restrict__ dst, int n4)
{
    int i = blockIdx.x * blockDim.x + threadIdx.x;
    if (i >= n4) return;
    float4 v = ((const float4*)src)[i];
    __half2 a = __floats2half2_rn(v.x, v.y);
    __half2 b = __floats2half2_rn(v.z, v.w);
    ((uint2*)dst)[i] = make_uint2(*(uint32_t*)&a, *(uint32_t*)&b);
}

// ===== transpose + convert, 64x64 tiles; z selects {wq, wk, wv} ======
__global__ void __launch_bounds__(256) tcvt_qkv_kernel(
    const float* __restrict__ wq, const float* __restrict__ wk,
    const float* __restrict__ wv, __half* __restrict__ wqkvt)
{
    const int z = blockIdx.z;
    const int N = (z == 0) ? DIMV : NKV * HD;
    if (blockIdx.x * 64 >= N) return;
    const float* w = (z == 0) ? wq : (z == 1) ? wk : wv;
    __half* dst = wqkvt + ((z == 0) ? 0 : (z == 1) ? (size_t)DIMV * DIMV
                                                   : (size_t)(DIMV + NKV*HD) * DIMV);
    __shared__ float t[64][65];
    const int n0 = blockIdx.x * 64, k0 = blockIdx.y * 64;
    const int tid = threadIdx.x;
    {
        int r = tid >> 4, c4 = (tid & 15) << 2;
#pragma unroll
        for (int i = 0; i < 4; i++) {
            float4 v = *(const float4*)(w + (size_t)(k0 + r + i * 16) * N + n0 + c4);
            t[r + i * 16][c4 + 0] = v.x;
            t[r + i * 16][c4 + 1] = v.y;
            t[r + i * 16][c4 + 2] = v.z;
            t[r + i * 16][c4 + 3] = v.w;
        }
    }
    __syncthreads();
    {
        int nl = tid >> 2, kc = (tid & 3) << 4;
        __half hv[16];
#pragma unroll
        for (int i = 0; i < 16; i++)
            hv[i] = __float2half(t[kc + i][nl]);
        *(uint4*)(dst + (size_t)(n0 + nl) * DIMV + k0 + kc)     = *(uint4*)&hv[0];
        *(uint4*)(dst + (size_t)(n0 + nl) * DIMV + k0 + kc + 8) = *(uint4*)&hv[8];
    }
}

__global__ void __launch_bounds__(256) tcvt_kernel(
    const float* __restrict__ w, __half* __restrict__ t16, int K, int N)
{
    __shared__ float t[64][65];
    const int n0 = blockIdx.x * 64, k0 = blockIdx.y * 64;
    const int tid = threadIdx.x;
    {
        int r = tid >> 4, c4 = (tid & 15) << 2;
#pragma unroll
        for (int i = 0; i < 4; i++) {
            float4 v = *(const float4*)(w + (size_t)(k0 + r + i * 16) * N + n0 + c4);
            t[r + i * 16][c4 + 0] = v.x;
            t[r + i * 16][c4 + 1] = v.y;
            t[r + i * 16][c4 + 2] = v.z;
            t[r + i * 16][c4 + 3] = v.w;
        }
    }
    __syncthreads();
    {
        int nl = tid >> 2, kc = (tid & 3) << 4;
        __half hv[16];
#pragma unroll
        for (int i = 0; i < 16; i++)
            hv[i] = __float2half(t[kc + i][nl]);
        *(uint4*)(t16 + (size_t)(n0 + nl) * K + k0 + kc)     = *(uint4*)&hv[0];
        *(uint4*)(t16 + (size_t)(n0 + nl) * K + k0 + kc + 8) = *(uint4*)&hv[8];
    }
}

// ====== persistent fp16 HMMA flash attention, 128-key KV, item stealing ======
#define AT_LDS 272
#define AT_QT  (128 * AT_LDS)
#define AT_KVT (128 * AT_LDS)
#define AT_STG (2 * AT_KVT)
#define ATTN_SMEM (AT_QT + 2 * AT_STG)      // 174080
#define N_ITEMS ((SEQ / 128) * NH * BATCH_)  // 1024

__global__ void __launch_bounds__(256, 1) attn_h(
    const __half* __restrict__ Qh, const __half* __restrict__ Kh,
    const __half* __restrict__ Vh, __half* __restrict__ Oh)
{
    extern __shared__ char sm_[];
    __shared__ unsigned int slot;
    uint32_t sb = smem_u32(sm_);
    const int tid = threadIdx.x, wid = tid >> 5, lane = tid & 31;

    const int bg = lane >> 3;
    const int kb_row = ((bg >> 1) << 3) + (lane & 7);
    const int kb_col = (bg & 1) << 3;

    while (true) {
        if (tid == 0) slot = atomicAdd(&g_ctr[1], 1u);
        __syncthreads();
        const unsigned int w = slot;
        if (w >= (unsigned int)N_ITEMS) break;

        const int qt = 15 - (w & 15);      // heavy tiles interleaved first
        const int h = (w >> 4) & 31;
        const int b = w >> 9;
        const int q0 = qt * 128, kvh = h >> 2;
        const int nkv = qt + 1;

        const char* Qg = (const char*)(Qh + ((size_t)(b * SEQ + q0) * NH + h) * HD);
        const char* Kg = (const char*)(Kh + ((size_t)(b * SEQ) * NKV + kvh) * HD);
        const char* Vg = (const char*)(Vh + ((size_t)(b * SEQ) * NKV + kvh) * HD);

        for (int c = tid; c < 128 * 16; c += 256) {
            int r = c >> 4, ch = (c & 15) << 4;
            cp16(sb + r * AT_LDS + ch, Qg + (size_t)r * 8192 + ch);
        }
        auto load_kv = [&](int kt, int s) {
            uint32_t st = sb + AT_QT + s * AT_STG;
            size_t gof = (size_t)kt * 128 * 2048;
            for (int c = tid; c < 128 * 16; c += 256) {
                int r = c >> 4, ch = (c & 15) << 4;
                size_t g = gof + (size_t)r * 2048 + ch;
                cp16(st + r * AT_LDS + ch,          Kg + g);
                cp16(st + AT_KVT + r * AT_LDS + ch, Vg + g);
            }
        };
        load_kv(0, 0);
        cp_commit();

        uint32_t qf[8][4];
        float oacc[16][4];
#pragma unroll
        for (int i = 0; i < 16; i++)
#pragma unroll
            for (int r = 0; r < 4; r++) oacc[i][r] = 0.f;
        float mrow0 = -1e30f, mrow1 = -1e30f, lrow0 = 0.f, lrow1 = 0.f;

        for (int kt = 0; kt < nkv; kt++) {
            cp_wait0();
            __syncthreads();
            if (kt + 1 < nkv) { load_kv(kt + 1, (kt + 1) & 1); cp_commit(); }

            if (kt == 0) {
                uint32_t qa = sb + (wid * 16 + (lane & 15)) * AT_LDS + ((lane >> 4) << 3) * 2;
#pragma unroll
                for (int kc = 0; kc < 8; kc++)
                    ldsm4(qf[kc][0], qf[kc][1], qf[kc][2], qf[kc][3], qa + kc * 32);
            }
            uint32_t st = sb + AT_QT + (kt & 1) * AT_STG;

            float sacc[16][4];
#pragma unroll
            for (int i = 0; i < 16; i++)
#pragma unroll
                for (int r = 0; r < 4; r++) sacc[i][r] = 0.f;

#pragma unroll
            for (int kc = 0; kc < 8; kc++) {
#pragma unroll
                for (int pr = 0; pr < 8; pr++) {
                    uint32_t bd = st + (pr * 16 + kb_row) * AT_LDS + (kc * 16 + kb_col) * 2;
                    uint32_t k0r, k1r, k2r, k3r;
                    ldsm4(k0r, k1r, k2r, k3r, bd);
                    mma16816(sacc[2*pr],   qf[kc], k0r, k1r);
                    mma16816(sacc[2*pr+1], qf[kc], k2r, k3r);
                }
            }

            const int k0g = kt * 128;
            const int rlo = q0 + wid * 16 + (lane >> 2);
            if (kt == nkv - 1) {
#pragma unroll
                for (int nj = 0; nj < 16; nj++) {
                    int key = k0g + nj * 8 + ((lane & 3) << 1);
                    if (key     > rlo)     sacc[nj][0] = -1e30f;
                    if (key + 1 > rlo)     sacc[nj][1] = -1e30f;
                    if (key     > rlo + 8) sacc[nj][2] = -1e30f;
                    if (key + 1 > rlo + 8) sacc[nj][3] = -1e30f;
                }
            }

            float mx0 = -1e30f, mx1 = -1e30f;
#pragma unroll
            for (int nj = 0; nj < 16; nj++) {
                mx0 = fmaxf(mx0, fmaxf(sacc[nj][0], sacc[nj][1]));
                mx1 = fmaxf(mx1, fmaxf(sacc[nj][2], sacc[nj][3]));
            }
            mx0 = fmaxf(mx0, __shfl_xor_sync(0xffffffffu, mx0, 1));
            mx0 = fmaxf(mx0, __shfl_xor_sync(0xffffffffu, mx0, 2));
            mx1 = fmaxf(mx1, __shfl_xor_sync(0xffffffffu, mx1, 1));
            mx1 = fmaxf(mx1, __shfl_xor_sync(0xffffffffu, mx1, 2));
            float mn0 = fmaxf(mrow0, mx0), mn1 = fmaxf(mrow1, mx1);
            float cr0 = __expf(mrow0 - mn0), cr1 = __expf(mrow1 - mn1);
            mrow0 = mn0; mrow1 = mn1;
            float sum0 = 0.f, sum1 = 0.f;
#pragma unroll
            for (int nj = 0; nj < 16; nj++) {
                float p0 = __expf(sacc[nj][0] - mn0); sacc[nj][0] = p0; sum0 += p0;
                float p1 = __expf(sacc[nj][1] - mn0); sacc[nj][1] = p1; sum0 += p1;
                float p2 = __expf(sacc[nj][2] - mn1); sacc[nj][2] = p2; sum1 += p2;
                float p3 = __expf(sacc[nj][3] - mn1); sacc[nj][3] = p3; sum1 += p3;
            }
            sum0 += __shfl_xor_sync(0xffffffffu, sum0, 1);
            sum0 += __shfl_xor_sync(0xffffffffu, sum0, 2);
            sum1 += __shfl_xor_sync(0xffffffffu, sum1, 1);
            sum1 += __shfl_xor_sync(0xffffffffu, sum1, 2);
            lrow0 = lrow0 * cr0 + sum0;
            lrow1 = lrow1 * cr1 + sum1;
#pragma unroll
            for (int nj = 0; nj < 16; nj++) {
                oacc[nj][0] *= cr0; oacc[nj][1] *= cr0;
                oacc[nj][2] *= cr1; oacc[nj][3] *= cr1;
            }

#pragma unroll
            for (int kc = 0; kc < 8; kc++) {
                uint32_t pa[4];
                pa[0] = packh(sacc[2*kc][0],   sacc[2*kc][1]);
                pa[1] = packh(sacc[2*kc][2],   sacc[2*kc][3]);
                pa[2] = packh(sacc[2*kc+1][0], sacc[2*kc+1][1]);
                pa[3] = packh(sacc[2*kc+1][2], sacc[2*kc+1][3]);
                uint32_t vrow = st + AT_KVT + (kc * 16 + (lane & 15)) * AT_LDS
                              + ((lane >> 4) << 3) * 2;
#pragma unroll
                for (int g = 0; g < 8; g++) {
                    uint32_t v0, v1, v2, v3;
                    ldsm4t(v0, v1, v2, v3, vrow + g * 32);
                    mma16816(oacc[2*g],   pa, v0, v1);
                    mma16816(oacc[2*g+1], pa, v2, v3);
                }
            }
        }
        __syncthreads();   // item boundary: smem + slot safe before next fetch

        float inv0 = 1.f / lrow0, inv1 = 1.f / lrow1;
        const int rlo = q0 + wid * 16 + (lane >> 2);
        size_t base_lo = ((size_t)(b * SEQ + rlo) * NH + h) * HD + ((lane & 3) << 1);
        size_t base_hi = base_lo + (size_t)8 * NH * HD;
#pragma unroll
        for (int nj = 0; nj < 16; nj++) {
            *(__half2*)(Oh + base_lo + nj * 8) =
                __floats2half2_rn(oacc[nj][0] * inv0, oacc[nj][1] * inv0);
            *(__half2*)(Oh + base_hi + nj * 8) =
                __floats2half2_rn(oacc[nj][2] * inv1, oacc[nj][3] * inv1);
        }
    }
}

// ============================ launch ======================================
extern "C" void kernel_launch(void* const* d_in, const int* in_sizes, int n_in,
                              void* d_out, int out_size)
{
    const float* x  = (const float*)d_in[0];
    const float* wq = (const float*)d_in[1];
    const float* wk = (const float*)d_in[2];
    const float* wv = (const float*)d_in[3];
    const float* wo = (const float*)d_in[4];
    const float* fc = (const float*)d_in[7];
    const float* fs = (const float*)d_in[8];
    float* out = (float*)d_out;
    (void)in_sizes; (void)n_in; (void)out_size;

    __half *xh, *wqkvt, *wot, *att, *qh, *kh, *vh;
    cudaGetSymbolAddress((void**)&xh,    g_xh);
    cudaGetSymbolAddress((void**)&wqkvt, g_wqkvt);
    cudaGetSymbolAddress((void**)&wot,   g_wot);
    cudaGetSymbolAddress((void**)&att,   g_att);
    cudaGetSymbolAddress((void**)&qh,    g_qh);
    cudaGetSymbolAddress((void**)&kh,    g_kh);
    cudaGetSymbolAddress((void**)&vh,    g_vh);

    cudaFuncSetAttribute(gemm_h, cudaFuncAttributeMaxDynamicSharedMemorySize, GEMM_SMEM);
    cudaFuncSetAttribute(attn_h, cudaFuncAttributeMaxDynamicSharedMemorySize, ATTN_SMEM);

    // ---- reset work-steal counters (each graph replay) ----
    reset_ctr_kernel<<<1, 1>>>();

    // ---- prep ----
    const int n4x = TOKENS * DIMV / 4;
    cvt_kernel<<<n4x / 256, 256>>>(x, xh, n4x);
    tcvt_qkv_kernel<<<dim3(DIMV / 64, DIMV / 64, 3), 256>>>(wq, wk, wv, wqkvt);
    tcvt_kernel<<<dim3(DIMV / 64, DIMV / 64), 256>>>(wo, wot, DIMV, DIMV);

    // ---- fused QKV projection + RoPE + fp16 epilogue (2 CTAs/SM, stealing) ----
    gemm_h<<<2 * NSM, 256, GEMM_SMEM>>>(xh, wqkvt, nullptr, qh, kh, vh, fc, fs,
                                        NQKV, DIMV, MT * (NQKV / BN), 1, 0);

    // ---- flash attention (persistent, 128-key KV tiles, stealing) ----
    attn_h<<<NSM, 256, ATTN_SMEM>>>(qh, kh, vh, att);

    // ---- output projection (fp32 out, stealing) ----
    gemm_h<<<2 * NSM, 256, GEMM_SMEM>>>(att, wot, out, nullptr, nullptr, nullptr, fc, fs,
                                        DIMV, DIMV, MT * (DIMV / BN), 0, 2);
}

// round 17
// speedup vs baseline: 1.2146x; 1.0285x over previous
#include <cuda_runtime.h>
#include <cuda_fp16.h>
#include <math.h>
#include <stdint.h>

#define BATCH_ 2
#define SEQ    2048
#define DIMV   4096
#define NH     32
#define NKV    8
#define HD     128
#define TOKENS (BATCH_*SEQ)   // 4096
#define NQKV   (DIMV + 2*NKV*HD)   // 6144
#define NSM    148

// ---------------- scratch (no cudaMalloc allowed) ----------------
__device__ __align__(1024) __half g_xh   [(size_t)TOKENS * DIMV];
__device__ __align__(1024) __half g_wqkvt[(size_t)NQKV * DIMV];
__device__ __align__(1024) __half g_wot  [(size_t)DIMV * DIMV];
__device__ __align__(1024) __half g_att  [(size_t)TOKENS * DIMV];
__device__ __align__(1024) __half g_qh   [(size_t)TOKENS * NH  * HD];
__device__ __align__(1024) __half g_kh   [(size_t)TOKENS * NKV * HD];
__device__ __align__(1024) __half g_vh   [(size_t)TOKENS * NKV * HD];
__device__ unsigned int g_ctr[3];   // work-steal counters: [0] qkv, [1] attn, [2] out

__global__ void reset_ctr_kernel() { g_ctr[0] = 0; g_ctr[1] = 0; g_ctr[2] = 0; }

// ================= helpers =================
__device__ __forceinline__ uint32_t smem_u32(const void* p) {
    return (uint32_t)__cvta_generic_to_shared(p);
}
__device__ __forceinline__ void cp16(uint32_t dst, const void* src) {
    asm volatile("cp.async.cg.shared.global [%0], [%1], 16;" :: "r"(dst), "l"(src));
}
__device__ __forceinline__ void cp_commit() {
    asm volatile("cp.async.commit_group;" ::: "memory");
}
__device__ __forceinline__ void cp_wait0() {
    asm volatile("cp.async.wait_group 0;" ::: "memory");
}
__device__ __forceinline__ void ldsm4(uint32_t& r0, uint32_t& r1, uint32_t& r2, uint32_t& r3,
                                      uint32_t addr) {
    asm volatile("ldmatrix.sync.aligned.m8n8.x4.shared.b16 {%0,%1,%2,%3}, [%4];"
                 : "=r"(r0), "=r"(r1), "=r"(r2), "=r"(r3) : "r"(addr));
}
__device__ __forceinline__ void ldsm4t(uint32_t& r0, uint32_t& r1, uint32_t& r2, uint32_t& r3,
                                       uint32_t addr) {
    asm volatile("ldmatrix.sync.aligned.m8n8.x4.trans.shared.b16 {%0,%1,%2,%3}, [%4];"
                 : "=r"(r0), "=r"(r1), "=r"(r2), "=r"(r3) : "r"(addr));
}
__device__ __forceinline__ void mma16816(float* c, const uint32_t* a, uint32_t b0, uint32_t b1) {
    asm volatile(
        "mma.sync.aligned.m16n8k16.row.col.f32.f16.f16.f32 "
        "{%0,%1,%2,%3}, {%4,%5,%6,%7}, {%8,%9}, {%0,%1,%2,%3};"
        : "+f"(c[0]), "+f"(c[1]), "+f"(c[2]), "+f"(c[3])
        : "r"(a[0]), "r"(a[1]), "r"(a[2]), "r"(a[3]), "r"(b0), "r"(b1));
}
__device__ __forceinline__ uint32_t packh(float a, float b) {
    __half2 t = __floats2half2_rn(a, b);
    return *reinterpret_cast<uint32_t*>(&t);
}

// ========== persistent fp16 HMMA GEMM (R13 config + tile stealing) ======
// C[M,N] = A[M,K] @ B[N,K]^T. BM=128, BN=128, BK=64, 2-stage, 2 CTAs/SM,
// 8 warps (2m x 4n), 64x32/warp, single-sync mainloop.
#define BM 128
#define BN 128
#define BK 64
#define LDSH  144
#define TILEH (128 * LDSH)
#define STGH  (2 * TILEH)
#define GEMM_SMEM (2 * STGH)       // 73728 -> 2 CTAs/SM
#define MT (TOKENS / BM)           // 32
#define QK_SCALE 0.08838834764831845f

__device__ __forceinline__ void load_stage(
    uint32_t sb, int s, const __half* A, const __half* B, int K, int k0, int tid)
{
    uint32_t st = sb + s * STGH;
#pragma unroll
    for (int t = 0; t < 4; t++) {
        int c = tid + t * 256;
        int row = c >> 3, ch = (c & 7) << 4;
        size_t go = ((size_t)row * K + k0) * 2 + ch;
        cp16(st + row * LDSH + ch,         (const char*)A + go);
        cp16(st + TILEH + row * LDSH + ch, (const char*)B + go);
    }
}

__global__ void __launch_bounds__(256, 2) gemm_h(
    const __half* __restrict__ A, const __half* __restrict__ B,
    float* __restrict__ Cf,
    __half* __restrict__ Qo, __half* __restrict__ Ko, __half* __restrict__ Vo,
    const float* __restrict__ fc, const float* __restrict__ fs,
    int N, int K, int ntiles, int mode, int ctr_idx)
{
    extern __shared__ char smem[];
    __shared__ unsigned int slot;
    uint32_t sb = smem_u32(smem);
    const int tid = threadIdx.x, wid = tid >> 5, lane = tid & 31;
    const int wm = wid & 1, wn = wid >> 1;

    const int a_row = wm * 64 + (lane & 15);
    const int a_col = (lane >> 4) << 3;
    const int bg = lane >> 3;
    const int b_row = wn * 32 + ((bg >> 1) << 3) + (lane & 7);
    const int b_col = (bg & 1) << 3;
    const int cr = lane >> 2, cc = (lane & 3) << 1;
    const int NIT = K / BK;

    while (true) {
        if (tid == 0) slot = atomicAdd(&g_ctr[ctr_idx], 1u);
        __syncthreads();
        const unsigned int tile = slot;
        if (tile >= (unsigned int)ntiles) break;

        const int bm0 = (tile % MT) * BM;           // m-fastest (B-block L2 reuse)
        const int bn0 = (tile / MT) * BN;
        const __half* pA = A + (size_t)bm0 * K;
        const __half* pB = B + (size_t)bn0 * K;

        float acc[4][4][4];
#pragma unroll
        for (int i = 0; i < 4; i++)
#pragma unroll
            for (int j = 0; j < 4; j++)
#pragma unroll
                for (int r = 0; r < 4; r++) acc[i][j][r] = 0.f;

        load_stage(sb, 0, pA, pB, K, 0, tid);
        cp_commit();

        for (int it = 0; it < NIT; ++it) {
            cp_wait0();
            __syncthreads();
            if (it + 1 < NIT) {
                load_stage(sb, (it + 1) & 1, pA, pB, K, (it + 1) * BK, tid);
                cp_commit();
            }

            uint32_t st = sb + (it & 1) * STGH;
#pragma unroll
            for (int ks = 0; ks < 4; ks++) {
                uint32_t af[4][4];
#pragma unroll
                for (int mi = 0; mi < 4; mi++) {
                    uint32_t ad = st + (a_row + mi * 16) * LDSH + (a_col + ks * 16) * 2;
                    ldsm4(af[mi][0], af[mi][1], af[mi][2], af[mi][3], ad);
                }
                uint32_t bf[4][2];
#pragma unroll
                for (int p = 0; p < 2; p++) {
                    uint32_t bd = st + TILEH + (b_row + p * 16) * LDSH + (b_col + ks * 16) * 2;
                    ldsm4(bf[2*p][0], bf[2*p][1], bf[2*p+1][0], bf[2*p+1][1], bd);
                }
#pragma unroll
                for (int mi = 0; mi < 4; mi++)
#pragma unroll
                    for (int ni = 0; ni < 4; ni++)
                        mma16816(acc[mi][ni], af[mi], bf[ni][0], bf[ni][1]);
            }
        }

        if (mode == 0) {
#pragma unroll
            for (int mi = 0; mi < 4; mi++) {
                int r0 = bm0 + wm * 64 + mi * 16 + cr;
#pragma unroll
                for (int ni = 0; ni < 4; ni++) {
                    int col = bn0 + wn * 32 + ni * 8 + cc;
                    *(float2*)(Cf + (size_t)r0 * N + col) =
                        make_float2(acc[mi][ni][0], acc[mi][ni][1]);
                    *(float2*)(Cf + (size_t)(r0 + 8) * N + col) =
                        make_float2(acc[mi][ni][2], acc[mi][ni][3]);
                }
            }
        } else {
            const int kind = (bn0 < DIMV) ? 0 : (bn0 < DIMV + NKV*HD) ? 1 : 2;
#pragma unroll
            for (int mi = 0; mi < 4; mi++) {
                int r0 = bm0 + wm * 64 + mi * 16 + cr;
#pragma unroll
                for (int ni = 0; ni < 4; ni++) {
                    int col = bn0 + wn * 32 + ni * 8 + cc;
#pragma unroll
                    for (int half_ = 0; half_ < 2; half_++) {
                        int row = r0 + half_ * 8;
                        float re = acc[mi][ni][half_ * 2];
                        float im = acc[mi][ni][half_ * 2 + 1];
                        __half2 o;
                        if (kind == 2) {
                            o = __floats2half2_rn(re, im);
                            *(__half2*)(Vo + (size_t)row * (NKV*HD) + (col - DIMV - NKV*HD)) = o;
                        } else {
                            int s = row & (SEQ - 1);
                            int j = (col & 127) >> 1;
                            float c  = fc[s * 64 + j];
                            float sn = fs[s * 64 + j];
                            if (kind == 0) {
                                o = __floats2half2_rn((re * c - im * sn) * QK_SCALE,
                                                      (re * sn + im * c) * QK_SCALE);
                                *(__half2*)(Qo + (size_t)row * DIMV + col) = o;
                            } else {
                                o = __floats2half2_rn((re * c - im * sn) * 1.0f,
                                                      (re * sn + im * c) * 1.0f);
                                *(__half2*)(Ko + (size_t)row * (NKV*HD) + (col - DIMV)) = o;
                            }
                        }
                    }
                }
            }
        }
        __syncthreads();   // protect smem stages + slot before next tile fetch
    }
}

// ================= fp32 -> fp16 convert (packed) =================
__global__ void cvt_kernel(const float* __restrict__ src, __half* __restrict__ dst, int n4)
{
    int i = blockIdx.x * blockDim.x + threadIdx.x;
    if (i >= n4) return;
    float4 v = ((const float4*)src)[i];
    __half2 a = __floats2half2_rn(v.x, v.y);
    __half2 b = __floats2half2_rn(v.z, v.w);
    ((uint2*)dst)[i] = make_uint2(*(uint32_t*)&a, *(uint32_t*)&b);
}

// ===== transpose + convert, 64x64 tiles; z selects {wq, wk, wv, wo} ======
__global__ void __launch_bounds__(256) tcvt_all_kernel(
    const float* __restrict__ wq, const float* __restrict__ wk,
    const float* __restrict__ wv, const float* __restrict__ wo,
    __half* __restrict__ wqkvt, __half* __restrict__ wot)
{
    const int z = blockIdx.z;
    const int N = (z == 1 || z == 2) ? NKV * HD : DIMV;
    if (blockIdx.x * 64 >= N) return;
    const float* w = (z == 0) ? wq : (z == 1) ? wk : (z == 2) ? wv : wo;
    __half* dst = (z == 3) ? wot
                : wqkvt + ((z == 0) ? 0 : (z == 1) ? (size_t)DIMV * DIMV
                                                   : (size_t)(DIMV + NKV*HD) * DIMV);
    __shared__ float t[64][65];
    const int n0 = blockIdx.x * 64, k0 = blockIdx.y * 64;
    const int tid = threadIdx.x;
    {
        int r = tid >> 4, c4 = (tid & 15) << 2;
#pragma unroll
        for (int i = 0; i < 4; i++) {
            float4 v = *(const float4*)(w + (size_t)(k0 + r + i * 16) * N + n0 + c4);
            t[r + i * 16][c4 + 0] = v.x;
            t[r + i * 16][c4 + 1] = v.y;
            t[r + i * 16][c4 + 2] = v.z;
            t[r + i * 16][c4 + 3] = v.w;
        }
    }
    __syncthreads();
    {
        int nl = tid >> 2, kc = (tid & 3) << 4;
        __half hv[16];
#pragma unroll
        for (int i = 0; i < 16; i++)
            hv[i] = __float2half(t[kc + i][nl]);
        *(uint4*)(dst + (size_t)(n0 + nl) * DIMV + k0 + kc)     = *(uint4*)&hv[0];
        *(uint4*)(dst + (size_t)(n0 + nl) * DIMV + k0 + kc + 8) = *(uint4*)&hv[8];
    }
}

// ====== persistent fp16 HMMA flash attention, 128-key KV, LPT stealing ======
#define AT_LDS 272
#define AT_QT  (128 * AT_LDS)
#define AT_KVT (128 * AT_LDS)
#define AT_STG (2 * AT_KVT)
#define ATTN_SMEM (AT_QT + 2 * AT_STG)      // 174080
#define N_ITEMS ((SEQ / 128) * NH * BATCH_)  // 1024

__global__ void __launch_bounds__(256, 1) attn_h(
    const __half* __restrict__ Qh, const __half* __restrict__ Kh,
    const __half* __restrict__ Vh, __half* __restrict__ Oh)
{
    extern __shared__ char sm_[];
    __shared__ unsigned int slot;
    uint32_t sb = smem_u32(sm_);
    const int tid = threadIdx.x, wid = tid >> 5, lane = tid & 31;

    const int bg = lane >> 3;
    const int kb_row = ((bg >> 1) << 3) + (lane & 7);
    const int kb_col = (bg & 1) << 3;

    while (true) {
        if (tid == 0) slot = atomicAdd(&g_ctr[1], 1u);
        __syncthreads();
        const unsigned int w = slot;
        if (w >= (unsigned int)N_ITEMS) break;

        // LPT order: all heaviest q-tiles issued first (qt descending globally)
        const int qt = 15 - (int)(w >> 6);
        const int h = (w >> 1) & 31;
        const int b = w & 1;
        const int q0 = qt * 128, kvh = h >> 2;
        const int nkv = qt + 1;

        const char* Qg = (const char*)(Qh + ((size_t)(b * SEQ + q0) * NH + h) * HD);
        const char* Kg = (const char*)(Kh + ((size_t)(b * SEQ) * NKV + kvh) * HD);
        const char* Vg = (const char*)(Vh + ((size_t)(b * SEQ) * NKV + kvh) * HD);

        for (int c = tid; c < 128 * 16; c += 256) {
            int r = c >> 4, ch = (c & 15) << 4;
            cp16(sb + r * AT_LDS + ch, Qg + (size_t)r * 8192 + ch);
        }
        auto load_kv = [&](int kt, int s) {
            uint32_t st = sb + AT_QT + s * AT_STG;
            size_t gof = (size_t)kt * 128 * 2048;
            for (int c = tid; c < 128 * 16; c += 256) {
                int r = c >> 4, ch = (c & 15) << 4;
                size_t g = gof + (size_t)r * 2048 + ch;
                cp16(st + r * AT_LDS + ch,          Kg + g);
                cp16(st + AT_KVT + r * AT_LDS + ch, Vg + g);
            }
        };
        load_kv(0, 0);
        cp_commit();

        uint32_t qf[8][4];
        float oacc[16][4];
#pragma unroll
        for (int i = 0; i < 16; i++)
#pragma unroll
            for (int r = 0; r < 4; r++) oacc[i][r] = 0.f;
        float mrow0 = -1e30f, mrow1 = -1e30f, lrow0 = 0.f, lrow1 = 0.f;

        for (int kt = 0; kt < nkv; kt++) {
            cp_wait0();
            __syncthreads();
            if (kt + 1 < nkv) { load_kv(kt + 1, (kt + 1) & 1); cp_commit(); }

            if (kt == 0) {
                uint32_t qa = sb + (wid * 16 + (lane & 15)) * AT_LDS + ((lane >> 4) << 3) * 2;
#pragma unroll
                for (int kc = 0; kc < 8; kc++)
                    ldsm4(qf[kc][0], qf[kc][1], qf[kc][2], qf[kc][3], qa + kc * 32);
            }
            uint32_t st = sb + AT_QT + (kt & 1) * AT_STG;

            float sacc[16][4];
#pragma unroll
            for (int i = 0; i < 16; i++)
#pragma unroll
                for (int r = 0; r < 4; r++) sacc[i][r] = 0.f;

#pragma unroll
            for (int kc = 0; kc < 8; kc++) {
#pragma unroll
                for (int pr = 0; pr < 8; pr++) {
                    uint32_t bd = st + (pr * 16 + kb_row) * AT_LDS + (kc * 16 + kb_col) * 2;
                    uint32_t k0r, k1r, k2r, k3r;
                    ldsm4(k0r, k1r, k2r, k3r, bd);
                    mma16816(sacc[2*pr],   qf[kc], k0r, k1r);
                    mma16816(sacc[2*pr+1], qf[kc], k2r, k3r);
                }
            }

            const int k0g = kt * 128;
            const int rlo = q0 + wid * 16 + (lane >> 2);
            if (kt == nkv - 1) {
#pragma unroll
                for (int nj = 0; nj < 16; nj++) {
                    int key = k0g + nj * 8 + ((lane & 3) << 1);
                    if (key     > rlo)     sacc[nj][0] = -1e30f;
                    if (key + 1 > rlo)     sacc[nj][1] = -1e30f;
                    if (key     > rlo + 8) sacc[nj][2] = -1e30f;
                    if (key + 1 > rlo + 8) sacc[nj][3] = -1e30f;
                }
            }

            float mx0 = -1e30f, mx1 = -1e30f;
#pragma unroll
            for (int nj = 0; nj < 16; nj++) {
                mx0 = fmaxf(mx0, fmaxf(sacc[nj][0], sacc[nj][1]));
                mx1 = fmaxf(mx1, fmaxf(sacc[nj][2], sacc[nj][3]));
            }
            mx0 = fmaxf(mx0, __shfl_xor_sync(0xffffffffu, mx0, 1));
            mx0 = fmaxf(mx0, __shfl_xor_sync(0xffffffffu, mx0, 2));
            mx1 = fmaxf(mx1, __shfl_xor_sync(0xffffffffu, mx1, 1));
            mx1 = fmaxf(mx1, __shfl_xor_sync(0xffffffffu, mx1, 2));
            float mn0 = fmaxf(mrow0, mx0), mn1 = fmaxf(mrow1, mx1);
            float cr0 = __expf(mrow0 - mn0), cr1 = __expf(mrow1 - mn1);
            mrow0 = mn0; mrow1 = mn1;
            float sum0 = 0.f, sum1 = 0.f;
#pragma unroll
            for (int nj = 0; nj < 16; nj++) {
                float p0 = __expf(sacc[nj][0] - mn0); sacc[nj][0] = p0; sum0 += p0;
                float p1 = __expf(sacc[nj][1] - mn0); sacc[nj][1] = p1; sum0 += p1;
                float p2 = __expf(sacc[nj][2] - mn1); sacc[nj][2] = p2; sum1 += p2;
                float p3 = __expf(sacc[nj][3] - mn1); sacc[nj][3] = p3; sum1 += p3;
            }
            sum0 += __shfl_xor_sync(0xffffffffu, sum0, 1);
            sum0 += __shfl_xor_sync(0xffffffffu, sum0, 2);
            sum1 += __shfl_xor_sync(0xffffffffu, sum1, 1);
            sum1 += __shfl_xor_sync(0xffffffffu, sum1, 2);
            lrow0 = lrow0 * cr0 + sum0;
            lrow1 = lrow1 * cr1 + sum1;
#pragma unroll
            for (int nj = 0; nj < 16; nj++) {
                oacc[nj][0] *= cr0; oacc[nj][1] *= cr0;
                oacc[nj][2] *= cr1; oacc[nj][3] *= cr1;
            }

#pragma unroll
            for (int kc = 0; kc < 8; kc++) {
                uint32_t pa[4];
                pa[0] = packh(sacc[2*kc][0],   sacc[2*kc][1]);
                pa[1] = packh(sacc[2*kc][2],   sacc[2*kc][3]);
                pa[2] = packh(sacc[2*kc+1][0], sacc[2*kc+1][1]);
                pa[3] = packh(sacc[2*kc+1][2], sacc[2*kc+1][3]);
                uint32_t vrow = st + AT_KVT + (kc * 16 + (lane & 15)) * AT_LDS
                              + ((lane >> 4) << 3) * 2;
#pragma unroll
                for (int g = 0; g < 8; g++) {
                    uint32_t v0, v1, v2, v3;
                    ldsm4t(v0, v1, v2, v3, vrow + g * 32);
                    mma16816(oacc[2*g],   pa, v0, v1);
                    mma16816(oacc[2*g+1], pa, v2, v3);
                }
            }
        }
        __syncthreads();   // item boundary: smem + slot safe before next fetch

        float inv0 = 1.f / lrow0, inv1 = 1.f / lrow1;
        const int rlo = q0 + wid * 16 + (lane >> 2);
        size_t base_lo = ((size_t)(b * SEQ + rlo) * NH + h) * HD + ((lane & 3) << 1);
        size_t base_hi = base_lo + (size_t)8 * NH * HD;
#pragma unroll
        for (int nj = 0; nj < 16; nj++) {
            *(__half2*)(Oh + base_lo + nj * 8) =
                __floats2half2_rn(oacc[nj][0] * inv0, oacc[nj][1] * inv0);
            *(__half2*)(Oh + base_hi + nj * 8) =
                __floats2half2_rn(oacc[nj][2] * inv1, oacc[nj][3] * inv1);
        }
    }
}

// ============================ launch ======================================
extern "C" void kernel_launch(void* const* d_in, const int* in_sizes, int n_in,
                              void* d_out, int out_size)
{
    const float* x  = (const float*)d_in[0];
    const float* wq = (const float*)d_in[1];
    const float* wk = (const float*)d_in[2];
    const float* wv = (const float*)d_in[3];
    const float* wo = (const float*)d_in[4];
    const float* fc = (const float*)d_in[7];
    const float* fs = (const float*)d_in[8];
    float* out = (float*)d_out;
    (void)in_sizes; (void)n_in; (void)out_size;

    __half *xh, *wqkvt, *wot, *att, *qh, *kh, *vh;
    cudaGetSymbolAddress((void**)&xh,    g_xh);
    cudaGetSymbolAddress((void**)&wqkvt, g_wqkvt);
    cudaGetSymbolAddress((void**)&wot,   g_wot);
    cudaGetSymbolAddress((void**)&att,   g_att);
    cudaGetSymbolAddress((void**)&qh,    g_qh);
    cudaGetSymbolAddress((void**)&kh,    g_kh);
    cudaGetSymbolAddress((void**)&vh,    g_vh);

    cudaFuncSetAttribute(gemm_h, cudaFuncAttributeMaxDynamicSharedMemorySize, GEMM_SMEM);
    cudaFuncSetAttribute(attn_h, cudaFuncAttributeMaxDynamicSharedMemorySize, ATTN_SMEM);

    // ---- reset work-steal counters (each graph replay) ----
    reset_ctr_kernel<<<1, 1>>>();

    // ---- prep ----
    const int n4x = TOKENS * DIMV / 4;
    cvt_kernel<<<n4x / 256, 256>>>(x, xh, n4x);
    tcvt_all_kernel<<<dim3(DIMV / 64, DIMV / 64, 4), 256>>>(wq, wk, wv, wo, wqkvt, wot);

    // ---- fused QKV projection + RoPE + fp16 epilogue (2 CTAs/SM, stealing) ----
    gemm_h<<<2 * NSM, 256, GEMM_SMEM>>>(xh, wqkvt, nullptr, qh, kh, vh, fc, fs,
                                        NQKV, DIMV, MT * (NQKV / BN), 1, 0);

    // ---- flash attention (persistent, 128-key KV tiles, LPT stealing) ----
    attn_h<<<NSM, 256, ATTN_SMEM>>>(qh, kh, vh, att);

    // ---- output projection (fp32 out, stealing) ----
    gemm_h<<<2 * NSM, 256, GEMM_SMEM>>>(att, wot, out, nullptr, nullptr, nullptr, fc, fs,
                                        DIMV, DIMV, MT * (DIMV / BN), 0, 2);
}